// round 9
// baseline (speedup 1.0000x reference)
#include <cuda_runtime.h>
#include <cstdint>
#include <math.h>

// bayes_55018531062578  (R9: R6 structure + pipe-balanced threefry)
//
// out[b] = sigmoid( BEVb[b]-BEVa[b] + (sum_{s<kapa} B[b,k*,s] - A[b,k*,s]) / kapa[b] )
// k*(b,s) = argmax_k ( log_softmax(mean)_k + gumbel(b,s,k) )
// gumbel: JAX partitionable threefry counter mode, bits = o0^o1 of
//   threefry2x32(key=(0,42), (0, i)),  u = bitcast((bits>>9)|0x3f800000)-1
// Fast argmax == argmin_k t_k * (1/w_k),  t_k = -log2(u_k+eps); near-tie
// fallback replays reference formula in accurate fp32.
//
// Threefry adds are forced onto the FMA pipe via IMAD (mad.lo.u32 with a
// runtime 'one' multiplier ptxas cannot fold), leaving only SHF+LOP3 on the
// ALU pipe: per-call alu 70 -> 40, fma +30. Balances the pipes (~2x alu
// headroom vs R6 where everything sat on alu at 71%).

#define EPSF 1e-20f

__device__ __forceinline__ uint32_t rotl32(uint32_t x, int r) {
    return __funnelshift_l(x, x, r);
}

// x += y, forced to IMAD (fma pipe): x = y*one + x
#define ADD_FMA(x, y) asm("mad.lo.u32 %0, %1, %2, %0;" : "+r"(x) : "r"(y), "r"(one))
// x += imm, forced to IMAD (fma pipe): x = one*imm + x
#define ADDI_FMA(x, imm) asm("mad.lo.u32 %0, %1, %2, %0;" : "+r"(x) : "r"(one), "n"(imm))

// threefry2x32, key (0,42), input (0, ctr); returns o0 ^ o1
__device__ __forceinline__ uint32_t threefry_xor(uint32_t ctr, uint32_t one) {
    const uint32_t KS1 = 42u;
    const uint32_t KS2 = 0x1BD11BDAu ^ 42u;

    uint32_t x0 = 0u;            // 0 + ks0
    uint32_t x1 = ctr + KS1;

#define TF_R(r) { ADD_FMA(x0, x1); x1 = rotl32(x1, (r)); x1 ^= x0; }
#define TF4(a,b,c,d) TF_R(a) TF_R(b) TF_R(c) TF_R(d)

    TF4(13,15,26,6)
    ADDI_FMA(x0, 42u);          ADDI_FMA(x1, (0x1BD11BDAu ^ 42u) + 1u);
    TF4(17,29,16,24)
    ADDI_FMA(x0, 0x1BD11BDAu ^ 42u); ADDI_FMA(x1, 2u);
    TF4(13,15,26,6)
    /* x0 += 0 */               ADDI_FMA(x1, 42u + 3u);
    TF4(17,29,16,24)
    ADDI_FMA(x0, 42u);          ADDI_FMA(x1, (0x1BD11BDAu ^ 42u) + 4u);
    TF4(13,15,26,6)
    ADDI_FMA(x0, 0x1BD11BDAu ^ 42u); ADDI_FMA(x1, 5u);
#undef TF4
#undef TF_R
    (void)KS2;
    return x0 ^ x1;
}

__device__ __forceinline__ float bits_to_uniform(uint32_t bits) {
    return __uint_as_float((bits >> 9) | 0x3f800000u) - 1.0f;
}

__global__ __launch_bounds__(256, 8)
void bayes_kernel(const float* __restrict__ A,
                  const float* __restrict__ Bm,
                  const float* __restrict__ BEVa,
                  const float* __restrict__ BEVb,
                  const int*   __restrict__ kapa,
                  const float* __restrict__ mean,
                  float* __restrict__ out,
                  int S, uint32_t one) {
    const int b    = blockIdx.x;
    const int tid  = threadIdx.x;
    const int warp = tid >> 5;
    const int lane = tid & 31;
    const int s    = tid;              // warp c covers s in [32c, 32c+32)

    __shared__ float red[8];

    const int kap = kapa[b];

    // Dead warp: publish zero partial, exit (exited threads skip the barrier).
    if ((warp << 5) >= kap) {
        if (lane == 0) red[warp] = 0.0f;
        return;
    }

    // Coalesced prefetch of all 8 candidates; the ~300-cycle threefry below
    // hides the load latency. Same line traffic as a post-selection gather.
    const float* Ab = A  + (size_t)b * 4 * S + s;
    const float* Bb = Bm + (size_t)b * 4 * S + s;
    const float a0 = Ab[0], a1 = Ab[S], a2 = Ab[2 * S], a3 = Ab[3 * S];
    const float v0 = Bb[0], v1 = Bb[S], v2 = Bb[2 * S], v3 = Bb[3 * S];

    // inverse softmax weights (common denominator cancels in the argmin)
    const float m0 = mean[0], m1 = mean[1], m2 = mean[2], m3 = mean[3];
    const float mx = fmaxf(fmaxf(m0, m1), fmaxf(m2, m3));
    const float e0 = __expf(m0 - mx), e1 = __expf(m1 - mx);
    const float e2 = __expf(m2 - mx), e3 = __expf(m3 - mx);
    const float iw[4] = {__fdividef(1.0f, e0), __fdividef(1.0f, e1),
                         __fdividef(1.0f, e2), __fdividef(1.0f, e3)};

    const uint32_t base = ((uint32_t)b * (uint32_t)S + (uint32_t)s) * 4u;

    float u[4], q[4];
#pragma unroll
    for (int k = 0; k < 4; k++) {
        const uint32_t bits = threefry_xor(base + (uint32_t)k, one);
        u[k] = bits_to_uniform(bits);
        const float t = -__log2f(u[k] + EPSF);   // > 0
        q[k] = t * iw[k];
    }

    // argmin with runner-up tracking
    int   kb = 0;
    float best = q[0], second = INFINITY;
    if (q[1] < best) { second = best; best = q[1]; kb = 1; } else second = q[1];
    if (q[2] < best) { second = best; best = q[2]; kb = 2; } else if (q[2] < second) second = q[2];
    if (q[3] < best) { second = best; best = q[3]; kb = 3; } else if (q[3] < second) second = q[3];

    if (second - best < best * 1e-3f) {
        // rare accurate fp32 fallback: exact reference formula
        const float se  = e0 + e1 + e2 + e3;
        const float lse = mx + logf(se);
        const float lg[4] = {m0 - lse, m1 - lse, m2 - lse, m3 - lse};
        float bs = -INFINITY; int kk = 0;
#pragma unroll
        for (int k = 0; k < 4; k++) {
            const float g  = -logf(-logf(u[k] + EPSF) + EPSF);
            const float sc = lg[k] + g;
            if (sc > bs) { bs = sc; kk = k; }
        }
        kb = kk;
    }

    // branchless select of the chosen k
    const float av = (kb == 0) ? a0 : (kb == 1) ? a1 : (kb == 2) ? a2 : a3;
    const float bv = (kb == 0) ? v0 : (kb == 1) ? v1 : (kb == 2) ? v2 : v3;
    float diff = (s < kap) ? (bv - av) : 0.0f;

#pragma unroll
    for (int o = 16; o > 0; o >>= 1)
        diff += __shfl_down_sync(0xffffffffu, diff, o);
    if (lane == 0) red[warp] = diff;

    __syncthreads();

    if (tid == 0) {
        float tot = 0.0f;
#pragma unroll
        for (int wi = 0; wi < 8; wi++) tot += red[wi];
        const float x = BEVb[b] - BEVa[b] + tot / (float)kap;
        out[b] = 1.0f / (1.0f + expf(-x));
    }
}

extern "C" void kernel_launch(void* const* d_in, const int* in_sizes, int n_in,
                              void* d_out, int out_size) {
    // metadata order: outcomeA, outcomeB, BEVa, BEVb, kapa, batch_size, features, mean
    const float* A    = (const float*)d_in[0];
    const float* Bm   = (const float*)d_in[1];
    const float* BEVa = (const float*)d_in[2];
    const float* BEVb = (const float*)d_in[3];
    const int*   kapa = (const int*)  d_in[4];

    // mean is the (only) 4-element input; locate it robustly from the tail
    const float* mean = (const float*)d_in[n_in - 1];
    for (int i = n_in - 1; i >= 5; --i) {
        if (in_sizes[i] == 4) { mean = (const float*)d_in[i]; break; }
    }

    float* out = (float*)d_out;

    const int B = in_sizes[2];                 // 16384
    const int S = in_sizes[0] / (4 * B);       // 256

    bayes_kernel<<<B, 256>>>(A, Bm, BEVa, BEVb, kapa, mean, out, S, 1u);
}

// round 10
// speedup vs baseline: 1.3161x; 1.3161x over previous
#include <cuda_runtime.h>
#include <cstdint>
#include <math.h>

// bayes_55018531062578  (R10: R6 structure + pre-RNG prefetch, no eps FADDs)
//
// out[b] = sigmoid( BEVb[b]-BEVa[b] + (sum_{s<kapa} B[b,k*,s] - A[b,k*,s]) / kapa[b] )
// k*(b,s) = argmax_k ( log_softmax(mean)_k + gumbel(b,s,k) )
// gumbel: JAX partitionable threefry counter mode, bits = o0^o1 of
//   threefry2x32(key=(0,42), (0, i)),  u = bitcast((bits>>9)|0x3f800000)-1
// Fast argmax == argmin_k t_k * (1/w_k),  t_k = -log2(u_k)  (u=0 -> +inf,
// never selected, matches reference where u=0 is the weakest gumbel).
// Near-tie fallback replays the reference formula (with eps) in fp32.

#define EPSF 1e-20f

__device__ __forceinline__ uint32_t rotl32(uint32_t x, int r) {
    return __funnelshift_l(x, x, r);
}

// threefry2x32, key (0,42), input (0, ctr); returns o0 ^ o1
__device__ __forceinline__ uint32_t threefry_xor(uint32_t ctr) {
    const uint32_t ks0 = 0u;
    const uint32_t ks1 = 42u;
    const uint32_t ks2 = 0x1BD11BDAu ^ 42u;

    uint32_t x0 = ks0;
    uint32_t x1 = ctr + ks1;

#define TF4(a,b,c,d) \
    x0 += x1; x1 = rotl32(x1,(a)); x1 ^= x0; \
    x0 += x1; x1 = rotl32(x1,(b)); x1 ^= x0; \
    x0 += x1; x1 = rotl32(x1,(c)); x1 ^= x0; \
    x0 += x1; x1 = rotl32(x1,(d)); x1 ^= x0;

    TF4(13,15,26,6)   x0 += ks1; x1 += ks2 + 1u;
    TF4(17,29,16,24)  x0 += ks2; x1 += ks0 + 2u;
    TF4(13,15,26,6)   x0 += ks0; x1 += ks1 + 3u;
    TF4(17,29,16,24)  x0 += ks1; x1 += ks2 + 4u;
    TF4(13,15,26,6)   x0 += ks2; x1 += ks0 + 5u;
#undef TF4
    return x0 ^ x1;
}

__device__ __forceinline__ float bits_to_uniform(uint32_t bits) {
    return __uint_as_float((bits >> 9) | 0x3f800000u) - 1.0f;
}

__global__ __launch_bounds__(256, 8)
void bayes_kernel(const float* __restrict__ A,
                  const float* __restrict__ Bm,
                  const float* __restrict__ BEVa,
                  const float* __restrict__ BEVb,
                  const int*   __restrict__ kapa,
                  const float* __restrict__ mean,
                  float* __restrict__ out,
                  int S) {
    const int b    = blockIdx.x;
    const int tid  = threadIdx.x;
    const int warp = tid >> 5;
    const int lane = tid & 31;
    const int s    = tid;              // warp c covers s in [32c, 32c+32)

    __shared__ float red[8];

    const int kap = kapa[b];

    // Dead warp: publish zero partial, exit (exited threads skip the barrier).
    if ((warp << 5) >= kap) {
        if (lane == 0) red[warp] = 0.0f;
        return;
    }

    // Coalesced prefetch of all 8 candidates BEFORE the RNG; the ~250-cycle
    // threefry chain hides the memory latency. Each warp's 32 lanes cover
    // exactly one 128B line per k-row, so traffic equals the post-hoc gather.
    const float* Ab = A  + (size_t)b * 4 * S + s;
    const float* Bb = Bm + (size_t)b * 4 * S + s;
    const float a0 = Ab[0], a1 = Ab[S], a2 = Ab[2 * S], a3 = Ab[3 * S];
    const float v0 = Bb[0], v1 = Bb[S], v2 = Bb[2 * S], v3 = Bb[3 * S];

    // inverse softmax weights (common denominator cancels in the argmin)
    const float m0 = mean[0], m1 = mean[1], m2 = mean[2], m3 = mean[3];
    const float mx = fmaxf(fmaxf(m0, m1), fmaxf(m2, m3));
    const float e0 = __expf(m0 - mx), e1 = __expf(m1 - mx);
    const float e2 = __expf(m2 - mx), e3 = __expf(m3 - mx);
    const float iw[4] = {__fdividef(1.0f, e0), __fdividef(1.0f, e1),
                         __fdividef(1.0f, e2), __fdividef(1.0f, e3)};

    const uint32_t base = ((uint32_t)b * (uint32_t)S + (uint32_t)s) * 4u;

    float u[4], q[4];
#pragma unroll
    for (int k = 0; k < 4; k++) {
        const uint32_t bits = threefry_xor(base + (uint32_t)k);
        u[k] = bits_to_uniform(bits);
        const float t = -__log2f(u[k]);   // u==0 -> +inf (never wins argmin)
        q[k] = t * iw[k];
    }

    // argmin with runner-up tracking
    int   kb = 0;
    float best = q[0], second = INFINITY;
    if (q[1] < best) { second = best; best = q[1]; kb = 1; } else second = q[1];
    if (q[2] < best) { second = best; best = q[2]; kb = 2; } else if (q[2] < second) second = q[2];
    if (q[3] < best) { second = best; best = q[3]; kb = 3; } else if (q[3] < second) second = q[3];

    if (second - best < best * 1e-3f) {
        // rare accurate fp32 fallback: exact reference formula (with eps)
        const float se  = e0 + e1 + e2 + e3;
        const float lse = mx + logf(se);
        const float lg[4] = {m0 - lse, m1 - lse, m2 - lse, m3 - lse};
        float bs = -INFINITY; int kk = 0;
#pragma unroll
        for (int k = 0; k < 4; k++) {
            const float g  = -logf(-logf(u[k] + EPSF) + EPSF);
            const float sc = lg[k] + g;
            if (sc > bs) { bs = sc; kk = k; }
        }
        kb = kk;
    }

    // branchless select of the chosen k
    const float av = (kb == 0) ? a0 : (kb == 1) ? a1 : (kb == 2) ? a2 : a3;
    const float bv = (kb == 0) ? v0 : (kb == 1) ? v1 : (kb == 2) ? v2 : v3;
    float diff = (s < kap) ? (bv - av) : 0.0f;

#pragma unroll
    for (int o = 16; o > 0; o >>= 1)
        diff += __shfl_down_sync(0xffffffffu, diff, o);
    if (lane == 0) red[warp] = diff;

    __syncthreads();

    if (tid == 0) {
        float tot = 0.0f;
#pragma unroll
        for (int wi = 0; wi < 8; wi++) tot += red[wi];
        const float x = BEVb[b] - BEVa[b] + tot / (float)kap;
        out[b] = 1.0f / (1.0f + expf(-x));
    }
}

extern "C" void kernel_launch(void* const* d_in, const int* in_sizes, int n_in,
                              void* d_out, int out_size) {
    // metadata order: outcomeA, outcomeB, BEVa, BEVb, kapa, batch_size, features, mean
    const float* A    = (const float*)d_in[0];
    const float* Bm   = (const float*)d_in[1];
    const float* BEVa = (const float*)d_in[2];
    const float* BEVb = (const float*)d_in[3];
    const int*   kapa = (const int*)  d_in[4];

    // mean is the (only) 4-element input; locate it robustly from the tail
    const float* mean = (const float*)d_in[n_in - 1];
    for (int i = n_in - 1; i >= 5; --i) {
        if (in_sizes[i] == 4) { mean = (const float*)d_in[i]; break; }
    }

    float* out = (float*)d_out;

    const int B = in_sizes[2];                 // 16384
    const int S = in_sizes[0] / (4 * B);       // 256

    bayes_kernel<<<B, 256>>>(A, Bm, BEVa, BEVb, kapa, mean, out, S);
}